// round 12
// baseline (speedup 1.0000x reference)
#include <cuda_runtime.h>
#include <cuda_fp16.h>
#include <math.h>
#include <stdint.h>

#define N_NODES  100000
#define N_EDGES  250000
#define LATENT   128
#define N_FEAT   16
#define OUT_DIM  128
#define D_IN     272

#define TILE_E   128
#define NTHREADS 288          // 8 compute warps + 1 producer warp
#define NCOMPUTE 256

// ---- fp16 transposed weights: per net, [N rows][Kp cols] K-major ----
#define L1_KP      320
#define WT_L1_OFF  0
#define WT_L2_OFF  (256*320)                  // 81920
#define WT_L3_OFF  (WT_L2_OFF + 256*256)      // 147456
#define WT_PER_NET (WT_L3_OFF + 128*256)      // 180224

__device__ __align__(16) __half g_Wt[2 * WT_PER_NET];

// ---- smem strides (halves): odd 16B-segment counts -> conflict-free ldmatrix ----
#define AS 328
#define HS 264
#define WS 72

// ---- smem layout (bytes) ----
#define SM_A     0
#define SM_H     (TILE_E * AS * 2)             // 83968
#define SM_W0    (SM_H + TILE_E * HS * 2)      // 151552
#define SM_W1    (SM_W0 + 256 * WS * 2)        // 188416
#define SM_BAR   (SM_W1 + 256 * WS * 2)        // 225280
#define SM_BIAS  (SM_BAR + 64)                 // 225344
#define SM_TOTAL (SM_BIAS + 1280 * 4)          // 230464

#define N_CHUNKS 26   // (5 + 4 + 4) per net x 2 nets, K=64 chunks

// ---------------------------------------------------------------------------
__device__ __forceinline__ uint32_t smem_u32(const void* p) {
    uint32_t a;
    asm("{ .reg .u64 t; cvta.to.shared.u64 t, %1; cvt.u32.u64 %0, t; }"
        : "=r"(a) : "l"(p));
    return a;
}

__device__ __forceinline__ void cp16(uint32_t s, const __half* g) {
    asm volatile("cp.async.ca.shared.global [%0], [%1], 16;"
                 :: "r"(s), "l"(__cvta_generic_to_global((const void*)g)) : "memory");
}

__device__ __forceinline__ void mbar_init(uint32_t addr, uint32_t cnt) {
    asm volatile("mbarrier.init.shared.b64 [%0], %1;" :: "r"(addr), "r"(cnt) : "memory");
}
__device__ __forceinline__ void mbar_arrive(uint32_t addr) {
    asm volatile("{\n\t.reg .b64 t;\n\tmbarrier.arrive.shared.b64 t, [%0];\n\t}"
                 :: "r"(addr) : "memory");
}
// .noinc is load-bearing: default form pre-increments the pending count.
__device__ __forceinline__ void cp_mbar_arrive_noinc(uint32_t addr) {
    asm volatile("cp.async.mbarrier.arrive.noinc.shared.b64 [%0];" :: "r"(addr) : "memory");
}
// Spin wait (round-6 form). The HW-sleep timeout variant regressed ~60us:
// all warps must wake at every chunk boundary and the CTA pays the max
// wakeup latency x 26 chunks. Spin resumes in ~60-90cyc and issue slots
// are not the binding resource (tensor pipe is).
__device__ __forceinline__ void mbar_wait(uint32_t addr, int parity) {
    uint32_t done = 0;
    while (!done) {
        asm volatile("{\n\t.reg .pred p;\n\t"
            "mbarrier.try_wait.parity.shared.b64 p, [%1], %2;\n\t"
            "selp.b32 %0, 1, 0, p;\n\t}"
            : "=r"(done) : "r"(addr), "r"((uint32_t)parity) : "memory");
    }
}
#define BAR_COMPUTE() asm volatile("bar.sync 1, 256;" ::: "memory")

#define LDSM_X4(r0, r1, r2, r3, addr) \
    asm volatile("ldmatrix.sync.aligned.m8n8.x4.shared.b16 {%0,%1,%2,%3}, [%4];" \
                 : "=r"(r0), "=r"(r1), "=r"(r2), "=r"(r3) : "r"(addr))

#define MMA16816(d, a, b0_, b1_) \
    asm volatile("mma.sync.aligned.m16n8k16.row.col.f32.f16.f16.f32 " \
                 "{%0,%1,%2,%3}, {%4,%5,%6,%7}, {%8,%9}, {%0,%1,%2,%3};" \
                 : "+f"((d)[0]), "+f"((d)[1]), "+f"((d)[2]), "+f"((d)[3]) \
                 : "r"((a)[0]), "r"((a)[1]), "r"((a)[2]), "r"((a)[3]), \
                   "r"(b0_), "r"(b1_))

__device__ __forceinline__ void red_add_v2(float* p, float a, float b) {
    asm volatile("red.global.add.v2.f32 [%0], {%1,%2};"
                 :: "l"(p), "f"(a), "f"(b) : "memory");
}

// ---------------------------------------------------------------------------
// weight prep: fp32 [K][N] -> fp16 [N][Kp] K-major via 32x32 smem-tiled
// transpose. Coalesced reads (n fastest) and coalesced fp16 writes (k fastest).
// Tiles per net: W1 10x8=80, W2 8x8=64, W3 8x4=32 -> 176; x2 nets = 352 blocks.
// ---------------------------------------------------------------------------
__global__ void prep_weights(const float* __restrict__ W1a, const float* __restrict__ W2a,
                             const float* __restrict__ W3a, const float* __restrict__ W1b,
                             const float* __restrict__ W2b, const float* __restrict__ W3b)
{
    __shared__ float tile[32][33];
    const int tx = threadIdx.x & 31, ty = threadIdx.x >> 5;   // 32 x 8
    int b = blockIdx.x;
    const int net = b / 176;
    int r = b - net * 176;

    const float* src; int K, Kp, N, tk, tn, dstOff;
    if (r < 80)       { src = net ? W1b : W1a; K = D_IN; Kp = L1_KP; N = 256;
                        tk = r % 10; tn = r / 10; dstOff = WT_L1_OFF; }
    else if (r < 144) { r -= 80; src = net ? W2b : W2a; K = 256; Kp = 256; N = 256;
                        tk = r & 7; tn = r >> 3; dstOff = WT_L2_OFF; }
    else              { r -= 144; src = net ? W3b : W3a; K = 256; Kp = 256; N = 128;
                        tk = r & 7; tn = r >> 3; dstOff = WT_L3_OFF; }

    const int k0 = tk * 32, n0 = tn * 32;
    #pragma unroll
    for (int i = 0; i < 4; i++) {
        int k = k0 + ty + i * 8;
        tile[ty + i * 8][tx] = (k < K) ? src[(size_t)k * N + n0 + tx] : 0.0f;
    }
    __syncthreads();

    __half* dst = g_Wt + (size_t)net * WT_PER_NET + dstOff;
    #pragma unroll
    for (int i = 0; i < 4; i++) {
        int n = n0 + ty + i * 8;
        dst[(size_t)n * Kp + k0 + tx] = __float2half(tile[tx][ty + i * 8]);
    }
}

// ---------------------------------------------------------------------------
// consumer: one layer's chunks (mbarrier-gated), acc += A @ W^T
// (round-6 structure: single-buffered frags)
// ---------------------------------------------------------------------------
template<int MT, int NT>
__device__ __forceinline__ void consume_layer(
    uint32_t aBase, int aStride, int nch,
    int mWarp, int nWarp, int lane,
    uint32_t sW0, uint32_t sW1, uint32_t barB,
    int& cc, int (&cph)[2],
    float (&acc)[MT][NT][4])
{
    for (int c = 0; c < nch; c++, cc++) {
        const int s = cc & 1;
        mbar_wait(barB + 8 * s, cph[s]); cph[s] ^= 1;       // full[s]
        const uint32_t wB = s ? sW1 : sW0;
        const int kA = c * 64;
        #pragma unroll
        for (int ks = 0; ks < 4; ks++) {
            const int k = ks * 16;
            uint32_t a[MT][4];
            #pragma unroll
            for (int mt = 0; mt < MT; mt++) {
                int row = mWarp + mt * 16 + (lane & 15);
                int col = kA + k + ((lane >> 4) << 3);
                LDSM_X4(a[mt][0], a[mt][1], a[mt][2], a[mt][3],
                        aBase + (uint32_t)(row * aStride + col) * 2);
            }
            uint32_t b[4][4];
            #pragma unroll
            for (int np = 0; np < NT / 2; np++) {
                int rowB = nWarp + np * 16 + ((lane >> 4) << 3) + (lane & 7);
                int colB = k + (((lane >> 3) & 1) << 3);
                LDSM_X4(b[np][0], b[np][1], b[np][2], b[np][3],
                        wB + (uint32_t)(rowB * WS + colB) * 2);
            }
            #pragma unroll
            for (int np = 0; np < NT / 2; np++)
                #pragma unroll
                for (int mt = 0; mt < MT; mt++) {
                    MMA16816(acc[mt][2 * np],     a[mt], b[np][0], b[np][1]);
                    MMA16816(acc[mt][2 * np + 1], a[mt], b[np][2], b[np][3]);
                }
        }
        mbar_arrive(barB + 16 + 8 * s);                      // empty[s]
    }
}

// ---------------------------------------------------------------------------
// main fused kernel: 1 CTA = 128 edges; warp 8 = weight producer
// ---------------------------------------------------------------------------
__global__ void __launch_bounds__(NTHREADS, 1)
edge_mlp_mma(const float* __restrict__ coords,
             const float* __restrict__ ef,
             const float* __restrict__ nf,
             const int*   __restrict__ p1,
             const int*   __restrict__ p2,
             const float* __restrict__ b1a, const float* __restrict__ b2a,
             const float* __restrict__ b3a,
             const float* __restrict__ b1b, const float* __restrict__ b2b,
             const float* __restrict__ b3b,
             float* __restrict__ out)
{
    extern __shared__ char smem[];
    const uint32_t sb = smem_u32(smem);
    __half* Ain   = (__half*)(smem + SM_A);
    __half* Hh    = (__half*)(smem + SM_H);
    float*  sbias = (float*)(smem + SM_BIAS);
    const uint32_t sW0 = sb + SM_W0, sW1 = sb + SM_W1, barB = sb + SM_BAR;
    const int tid = threadIdx.x, w = tid >> 5, lane = tid & 31;
    const int base = blockIdx.x * TILE_E;

    if (tid == 0) {
        mbar_init(barB + 0, 32);   // full0  (producer lanes, cp-arrive noinc)
        mbar_init(barB + 8, 32);   // full1
        mbar_init(barB + 16, 256); // empty0 (compute threads)
        mbar_init(barB + 24, 256); // empty1
    }
    __syncthreads();

    // ======================= producer warp =======================
    if (w == 8) {
        int pph[2] = {0, 0};
        #pragma unroll 1
        for (int c = 0; c < N_CHUNKS; c++) {
            const int s = c & 1;
            if (c >= 2) { mbar_wait(barB + 16 + 8 * s, pph[s]); pph[s] ^= 1; }
            const int net = (c >= 13) ? 1 : 0;
            const int lc  = c - net * 13;
            const __half* src; int Kp, rows, k0;
            if (lc < 5)      { src = g_Wt + (size_t)net * WT_PER_NET + WT_L1_OFF; Kp = L1_KP; rows = 256; k0 = lc * 64; }
            else if (lc < 9) { src = g_Wt + (size_t)net * WT_PER_NET + WT_L2_OFF; Kp = 256;  rows = 256; k0 = (lc - 5) * 64; }
            else             { src = g_Wt + (size_t)net * WT_PER_NET + WT_L3_OFF; Kp = 256;  rows = 128; k0 = (lc - 9) * 64; }
            const uint32_t dst = s ? sW1 : sW0;
            for (int i = lane; i < rows * 8; i += 32) {
                int n = i >> 3, seg = i & 7;
                cp16(dst + (uint32_t)(n * WS + seg * 8) * 2,
                     src + (size_t)n * Kp + k0 + seg * 8);
            }
            cp_mbar_arrive_noinc(barB + 8 * s);
        }
        return;
    }

    // ======================= compute warps (0..7) =======================
    // ---- biases to smem once: [net*640 + {B1:0, B2:256, B3:512}] ----
    for (int i = tid; i < 256; i += NCOMPUTE) {
        sbias[i]        = b1a[i];
        sbias[256 + i]  = b2a[i];
        sbias[640 + i]  = b1b[i];
        sbias[896 + i]  = b2b[i];
    }
    for (int i = tid; i < 128; i += NCOMPUTE) {
        sbias[512 + i]  = b3a[i];
        sbias[1152 + i] = b3b[i];
    }

    // ---- gather: A[e] = [ef(16) | c1(128) | c2(128) | pad(48)] as fp16 ----
    for (int idx = tid; idx < TILE_E * N_FEAT; idx += NCOMPUTE) {
        int e = idx >> 4, k = idx & 15;
        int ge = base + e; if (ge >= N_EDGES) ge = N_EDGES - 1;
        Ain[e * AS + k] = __float2half(ef[(size_t)ge * N_FEAT + k]);
    }
    for (int e = w; e < TILE_E; e += 8) {
        int ge = base + e; if (ge >= N_EDGES) ge = N_EDGES - 1;
        const float4 v1 = ((const float4*)(coords + (size_t)p1[ge] * LATENT))[lane];
        const float4 v2 = ((const float4*)(coords + (size_t)p2[ge] * LATENT))[lane];
        __half2* d1 = (__half2*)(Ain + e * AS + N_FEAT + lane * 4);
        d1[0] = __floats2half2_rn(v1.x, v1.y);
        d1[1] = __floats2half2_rn(v1.z, v1.w);
        __half2* d2 = (__half2*)(Ain + e * AS + N_FEAT + LATENT + lane * 4);
        d2[0] = __floats2half2_rn(v2.x, v2.y);
        d2[1] = __floats2half2_rn(v2.z, v2.w);
    }
    for (int idx = tid; idx < TILE_E * 24; idx += NCOMPUTE) {   // zero cols 272..319
        int e = idx / 24, c = D_IN + (idx % 24) * 2;
        *(uint32_t*)(Ain + e * AS + c) = 0u;
    }
    BAR_COMPUTE();

    const int mW  = (w & 1) * 64, nW  = (w >> 1) * 64;   // L1/L2: 64x64 warp tiles
    const int mW3 = (w & 3) * 32, nW3 = (w >> 2) * 64;   // L3:    32x64 warp tiles

    int cc = 0;
    int cph[2] = {0, 0};

    #pragma unroll 1
    for (int net = 0; net < 2; net++) {
        const int* port = net ? p2 : p1;
        const int boff = net * 640;

        // ===== layer 1 =====
        {
            float acc[4][8][4] = {};
            consume_layer<4, 8>(sb + SM_A, AS, 5, mW, nW, lane, sW0, sW1, barB, cc, cph, acc);
            BAR_COMPUTE();
            #pragma unroll
            for (int mt = 0; mt < 4; mt++) {
                int r0 = mW + mt * 16 + (lane >> 2);
                #pragma unroll
                for (int nt = 0; nt < 8; nt++) {
                    int col = nW + nt * 8 + 2 * (lane & 3);
                    float bv0 = sbias[boff + col], bv1 = sbias[boff + col + 1];
                    *(__half2*)(Hh + r0 * HS + col) = __floats2half2_rn(
                        fmaxf(acc[mt][nt][0] + bv0, 0.f), fmaxf(acc[mt][nt][1] + bv1, 0.f));
                    *(__half2*)(Hh + (r0 + 8) * HS + col) = __floats2half2_rn(
                        fmaxf(acc[mt][nt][2] + bv0, 0.f), fmaxf(acc[mt][nt][3] + bv1, 0.f));
                }
            }
            BAR_COMPUTE();
        }

        // ===== layer 2 (in-place h) =====
        {
            float acc[4][8][4] = {};
            consume_layer<4, 8>(sb + SM_H, HS, 4, mW, nW, lane, sW0, sW1, barB, cc, cph, acc);
            BAR_COMPUTE();
            #pragma unroll
            for (int mt = 0; mt < 4; mt++) {
                int r0 = mW + mt * 16 + (lane >> 2);
                #pragma unroll
                for (int nt = 0; nt < 8; nt++) {
                    int col = nW + nt * 8 + 2 * (lane & 3);
                    float bv0 = sbias[boff + 256 + col], bv1 = sbias[boff + 256 + col + 1];
                    *(__half2*)(Hh + r0 * HS + col) = __floats2half2_rn(
                        fmaxf(acc[mt][nt][0] + bv0, 0.f), fmaxf(acc[mt][nt][1] + bv1, 0.f));
                    *(__half2*)(Hh + (r0 + 8) * HS + col) = __floats2half2_rn(
                        fmaxf(acc[mt][nt][2] + bv0, 0.f), fmaxf(acc[mt][nt][3] + bv1, 0.f));
                }
            }
            BAR_COMPUTE();
        }

        // ===== layer 3 + scatter =====
        {
            float acc[2][8][4] = {};
            consume_layer<2, 8>(sb + SM_H, HS, 4, mW3, nW3, lane, sW0, sW1, barB, cc, cph, acc);
            BAR_COMPUTE();   // all Hh reads done before net1 epilogue overwrites
            #pragma unroll
            for (int mt = 0; mt < 2; mt++) {
                int r0  = mW3 + mt * 16 + (lane >> 2);
                int ge0 = base + r0, ge1 = ge0 + 8;
                bool v0 = ge0 < N_EDGES, v1 = ge1 < N_EDGES;
                float nf0 = v0 ? nf[ge0] : 0.f;
                float nf1 = v1 ? nf[ge1] : 0.f;
                float* o0 = out + (size_t)(v0 ? port[ge0] : 0) * OUT_DIM;
                float* o1 = out + (size_t)(v1 ? port[ge1] : 0) * OUT_DIM;
                #pragma unroll
                for (int nt = 0; nt < 8; nt++) {
                    int col = nW3 + nt * 8 + 2 * (lane & 3);
                    float bv0 = sbias[boff + 512 + col], bv1 = sbias[boff + 512 + col + 1];
                    if (v0) red_add_v2(o0 + col, (acc[mt][nt][0] + bv0) * nf0,
                                                 (acc[mt][nt][1] + bv1) * nf0);
                    if (v1) red_add_v2(o1 + col, (acc[mt][nt][2] + bv0) * nf1,
                                                 (acc[mt][nt][3] + bv1) * nf1);
                }
            }
        }
    }
}

// ---------------------------------------------------------------------------
__global__ void zero_kernel(float4* __restrict__ out, int n4)
{
    int i = blockIdx.x * blockDim.x + threadIdx.x;
    if (i < n4) out[i] = make_float4(0.f, 0.f, 0.f, 0.f);
}

__global__ void tanh_kernel(float4* __restrict__ out, int n4)
{
    int i = blockIdx.x * blockDim.x + threadIdx.x;
    if (i < n4) {
        float4 v = out[i];
        v.x = tanhf(v.x); v.y = tanhf(v.y);
        v.z = tanhf(v.z); v.w = tanhf(v.w);
        out[i] = v;
    }
}

extern "C" void kernel_launch(void* const* d_in, const int* in_sizes, int n_in,
                              void* d_out, int out_size)
{
    const float* coords = (const float*)d_in[0];
    const float* ef     = (const float*)d_in[1];
    const float* nf     = (const float*)d_in[2];
    const int*   p1     = (const int*)  d_in[3];
    const int*   p2     = (const int*)  d_in[4];
    const float* W1a = (const float*)d_in[5];  const float* b1a = (const float*)d_in[6];
    const float* W2a = (const float*)d_in[7];  const float* b2a = (const float*)d_in[8];
    const float* W3a = (const float*)d_in[9];  const float* b3a = (const float*)d_in[10];
    const float* W1b = (const float*)d_in[11]; const float* b1b = (const float*)d_in[12];
    const float* W2b = (const float*)d_in[13]; const float* b2b = (const float*)d_in[14];
    const float* W3b = (const float*)d_in[15]; const float* b3b = (const float*)d_in[16];
    float* out = (float*)d_out;

    const int n  = N_NODES * OUT_DIM;
    const int n4 = n / 4;

    cudaFuncSetAttribute(edge_mlp_mma,
                         cudaFuncAttributeMaxDynamicSharedMemorySize, SM_TOTAL);

    prep_weights<<<352, 256>>>(W1a, W2a, W3a, W1b, W2b, W3b);
    zero_kernel<<<(n4 + 255) / 256, 256>>>((float4*)out, n4);

    const int grid = (N_EDGES + TILE_E - 1) / TILE_E;
    edge_mlp_mma<<<grid, NTHREADS, SM_TOTAL>>>(
        coords, ef, nf, p1, p2,
        b1a, b2a, b3a, b1b, b2b, b3b, out);

    tanh_kernel<<<(n4 + 255) / 256, 256>>>((float4*)out, n4);
}

// round 13
// speedup vs baseline: 1.4932x; 1.4932x over previous
#include <cuda_runtime.h>
#include <cuda_fp16.h>
#include <math.h>
#include <stdint.h>

#define N_NODES  100000
#define N_EDGES  250000
#define LATENT   128
#define N_FEAT   16
#define OUT_DIM  128
#define D_IN     272

#define TILE_E   128
#define NTHREADS 288          // 8 compute warps + 1 producer warp
#define NCOMPUTE 256

// ---- fp16 transposed weights: per net, [N rows][Kp cols] K-major ----
#define L1_KP      320
#define WT_L1_OFF  0
#define WT_L2_OFF  (256*320)                  // 81920
#define WT_L3_OFF  (WT_L2_OFF + 256*256)      // 147456
#define WT_PER_NET (WT_L3_OFF + 128*256)      // 180224

__device__ __align__(16) __half g_Wt[2 * WT_PER_NET];

// ---- smem strides (halves): odd 16B-segment counts -> conflict-free ldmatrix ----
#define AS 328
#define HS 264
#define WS 72

// ---- smem layout (bytes) ----
#define SM_A    0
#define SM_H    (TILE_E * AS * 2)              // 83968
#define SM_W0   (SM_H + TILE_E * HS * 2)       // 151552
#define SM_W1   (SM_W0 + 256 * WS * 2)         // 188416
#define SM_BAR  (SM_W1 + 256 * WS * 2)         // 225280
#define SM_TOTAL (SM_BAR + 32)                 // 225312

#define N_CHUNKS 26   // (5 + 4 + 4) per net x 2 nets

// ---------------------------------------------------------------------------
__device__ __forceinline__ uint32_t smem_u32(const void* p) {
    uint32_t a;
    asm("{ .reg .u64 t; cvta.to.shared.u64 t, %1; cvt.u32.u64 %0, t; }"
        : "=r"(a) : "l"(p));
    return a;
}

__device__ __forceinline__ void cp16(uint32_t s, const __half* g) {
    asm volatile("cp.async.ca.shared.global [%0], [%1], 16;"
                 :: "r"(s), "l"(__cvta_generic_to_global((const void*)g)) : "memory");
}

__device__ __forceinline__ void mbar_init(uint32_t addr, uint32_t cnt) {
    asm volatile("mbarrier.init.shared.b64 [%0], %1;" :: "r"(addr), "r"(cnt) : "memory");
}
__device__ __forceinline__ void mbar_arrive(uint32_t addr) {
    asm volatile("{\n\t.reg .b64 t;\n\tmbarrier.arrive.shared.b64 t, [%0];\n\t}"
                 :: "r"(addr) : "memory");
}
// .noinc is load-bearing: the default form pre-increments the pending count
// (net-zero on the phase), which deadlocks the consumers.
__device__ __forceinline__ void cp_mbar_arrive_noinc(uint32_t addr) {
    asm volatile("cp.async.mbarrier.arrive.noinc.shared.b64 [%0];" :: "r"(addr) : "memory");
}
// Spin wait (round-6 form; HW-sleep timeout variant measured slower).
__device__ __forceinline__ void mbar_wait(uint32_t addr, int parity) {
    uint32_t done = 0;
    while (!done) {
        asm volatile("{\n\t.reg .pred p;\n\t"
            "mbarrier.try_wait.parity.shared.b64 p, [%1], %2;\n\t"
            "selp.b32 %0, 1, 0, p;\n\t}"
            : "=r"(done) : "r"(addr), "r"((uint32_t)parity) : "memory");
    }
}
#define BAR_COMPUTE() asm volatile("bar.sync 1, 256;" ::: "memory")

#define LDSM_X4(r0, r1, r2, r3, addr) \
    asm volatile("ldmatrix.sync.aligned.m8n8.x4.shared.b16 {%0,%1,%2,%3}, [%4];" \
                 : "=r"(r0), "=r"(r1), "=r"(r2), "=r"(r3) : "r"(addr))

#define MMA16816(d, a, b0_, b1_) \
    asm volatile("mma.sync.aligned.m16n8k16.row.col.f32.f16.f16.f32 " \
                 "{%0,%1,%2,%3}, {%4,%5,%6,%7}, {%8,%9}, {%0,%1,%2,%3};" \
                 : "+f"((d)[0]), "+f"((d)[1]), "+f"((d)[2]), "+f"((d)[3]) \
                 : "r"((a)[0]), "r"((a)[1]), "r"((a)[2]), "r"((a)[3]), \
                   "r"(b0_), "r"(b1_))

__device__ __forceinline__ void red_add_v2(float* p, float a, float b) {
    asm volatile("red.global.add.v2.f32 [%0], {%1,%2};"
                 :: "l"(p), "f"(a), "f"(b) : "memory");
}

// ---------------------------------------------------------------------------
// weight prep: fp32 [K][N] -> fp16 [N][Kp] K-major via 32x32 smem-tiled
// transpose. Coalesced reads (n fastest) and coalesced fp16 writes (k fastest).
// Tiles per net: W1 10x8=80, W2 8x8=64, W3 8x4=32 -> 176; x2 nets = 352 blocks.
// ---------------------------------------------------------------------------
__global__ void prep_weights(const float* __restrict__ W1a, const float* __restrict__ W2a,
                             const float* __restrict__ W3a, const float* __restrict__ W1b,
                             const float* __restrict__ W2b, const float* __restrict__ W3b)
{
    __shared__ float tile[32][33];
    const int tx = threadIdx.x & 31, ty = threadIdx.x >> 5;   // 32 x 8
    int b = blockIdx.x;
    const int net = b / 176;
    int r = b - net * 176;

    const float* src; int K, Kp, N, tk, tn, dstOff;
    if (r < 80)       { src = net ? W1b : W1a; K = D_IN; Kp = L1_KP; N = 256;
                        tk = r % 10; tn = r / 10; dstOff = WT_L1_OFF; }
    else if (r < 144) { r -= 80; src = net ? W2b : W2a; K = 256; Kp = 256; N = 256;
                        tk = r & 7; tn = r >> 3; dstOff = WT_L2_OFF; }
    else              { r -= 144; src = net ? W3b : W3a; K = 256; Kp = 256; N = 128;
                        tk = r & 7; tn = r >> 3; dstOff = WT_L3_OFF; }

    const int k0 = tk * 32, n0 = tn * 32;
    #pragma unroll
    for (int i = 0; i < 4; i++) {
        int k = k0 + ty + i * 8;
        tile[ty + i * 8][tx] = (k < K) ? src[(size_t)k * N + n0 + tx] : 0.0f;
    }
    __syncthreads();

    __half* dst = g_Wt + (size_t)net * WT_PER_NET + dstOff;
    #pragma unroll
    for (int i = 0; i < 4; i++) {
        int n = n0 + ty + i * 8;
        dst[(size_t)n * Kp + k0 + tx] = __float2half(tile[tx][ty + i * 8]);
    }
}

// ---------------------------------------------------------------------------
// consumer: one layer's chunks (mbarrier-gated), acc += A @ W^T
// ---------------------------------------------------------------------------
template<int MT, int NT>
__device__ __forceinline__ void consume_layer(
    uint32_t aBase, int aStride, int nch,
    int mWarp, int nWarp, int lane,
    uint32_t sW0, uint32_t sW1, uint32_t barB,
    int& cc, int (&cph)[2],
    float (&acc)[MT][NT][4])
{
    for (int c = 0; c < nch; c++, cc++) {
        const int s = cc & 1;
        mbar_wait(barB + 8 * s, cph[s]); cph[s] ^= 1;       // full[s]
        const uint32_t wB = s ? sW1 : sW0;
        const int kA = c * 64;
        #pragma unroll
        for (int ks = 0; ks < 4; ks++) {
            const int k = ks * 16;
            uint32_t a[MT][4];
            #pragma unroll
            for (int mt = 0; mt < MT; mt++) {
                int row = mWarp + mt * 16 + (lane & 15);
                int col = kA + k + ((lane >> 4) << 3);
                LDSM_X4(a[mt][0], a[mt][1], a[mt][2], a[mt][3],
                        aBase + (uint32_t)(row * aStride + col) * 2);
            }
            uint32_t b[4][4];
            #pragma unroll
            for (int np = 0; np < NT / 2; np++) {
                int rowB = nWarp + np * 16 + ((lane >> 4) << 3) + (lane & 7);
                int colB = k + (((lane >> 3) & 1) << 3);
                LDSM_X4(b[np][0], b[np][1], b[np][2], b[np][3],
                        wB + (uint32_t)(rowB * WS + colB) * 2);
            }
            #pragma unroll
            for (int np = 0; np < NT / 2; np++)
                #pragma unroll
                for (int mt = 0; mt < MT; mt++) {
                    MMA16816(acc[mt][2 * np],     a[mt], b[np][0], b[np][1]);
                    MMA16816(acc[mt][2 * np + 1], a[mt], b[np][2], b[np][3]);
                }
        }
        mbar_arrive(barB + 16 + 8 * s);                      // empty[s]
    }
}

// ---------------------------------------------------------------------------
// main fused kernel: 1 CTA = 128 edges; warp 8 = weight producer
// ---------------------------------------------------------------------------
__global__ void __launch_bounds__(NTHREADS, 1)
edge_mlp_mma(const float* __restrict__ coords,
             const float* __restrict__ ef,
             const float* __restrict__ nf,
             const int*   __restrict__ p1,
             const int*   __restrict__ p2,
             const float* __restrict__ b1a, const float* __restrict__ b2a,
             const float* __restrict__ b3a,
             const float* __restrict__ b1b, const float* __restrict__ b2b,
             const float* __restrict__ b3b,
             float* __restrict__ out)
{
    extern __shared__ char smem[];
    const uint32_t sb = smem_u32(smem);
    __half* Ain   = (__half*)(smem + SM_A);
    __half* Hh    = (__half*)(smem + SM_H);
    const uint32_t sW0 = sb + SM_W0, sW1 = sb + SM_W1, barB = sb + SM_BAR;
    const int tid = threadIdx.x, w = tid >> 5, lane = tid & 31;
    const int base = blockIdx.x * TILE_E;

    if (tid == 0) {
        mbar_init(barB + 0, 32);   // full0  (producer lanes, cp-arrive noinc)
        mbar_init(barB + 8, 32);   // full1
        mbar_init(barB + 16, 256); // empty0 (compute threads)
        mbar_init(barB + 24, 256); // empty1
    }
    __syncthreads();

    // ======================= producer warp =======================
    if (w == 8) {
        int pph[2] = {0, 0};
        #pragma unroll 1
        for (int c = 0; c < N_CHUNKS; c++) {
            const int s = c & 1;
            if (c >= 2) { mbar_wait(barB + 16 + 8 * s, pph[s]); pph[s] ^= 1; }
            const int net = (c >= 13) ? 1 : 0;
            const int lc  = c - net * 13;
            const __half* src; int Kp, rows, k0;
            if (lc < 5)      { src = g_Wt + (size_t)net * WT_PER_NET + WT_L1_OFF; Kp = L1_KP; rows = 256; k0 = lc * 64; }
            else if (lc < 9) { src = g_Wt + (size_t)net * WT_PER_NET + WT_L2_OFF; Kp = 256;  rows = 256; k0 = (lc - 5) * 64; }
            else             { src = g_Wt + (size_t)net * WT_PER_NET + WT_L3_OFF; Kp = 256;  rows = 128; k0 = (lc - 9) * 64; }
            const uint32_t dst = s ? sW1 : sW0;
            for (int i = lane; i < rows * 8; i += 32) {
                int n = i >> 3, seg = i & 7;
                cp16(dst + (uint32_t)(n * WS + seg * 8) * 2,
                     src + (size_t)n * Kp + k0 + seg * 8);
            }
            cp_mbar_arrive_noinc(barB + 8 * s);   // full[s] fires when this lane's cps land
        }
        return;
    }

    // ======================= compute warps (0..7) =======================
    // ---- gather: A[e] = [ef(16) | c1(128) | c2(128) | pad(48)] as fp16 ----
    for (int idx = tid; idx < TILE_E * N_FEAT; idx += NCOMPUTE) {
        int e = idx >> 4, k = idx & 15;
        int ge = base + e; if (ge >= N_EDGES) ge = N_EDGES - 1;
        Ain[e * AS + k] = __float2half(ef[(size_t)ge * N_FEAT + k]);
    }
    for (int e = w; e < TILE_E; e += 8) {
        int ge = base + e; if (ge >= N_EDGES) ge = N_EDGES - 1;
        const float4 v1 = ((const float4*)(coords + (size_t)p1[ge] * LATENT))[lane];
        const float4 v2 = ((const float4*)(coords + (size_t)p2[ge] * LATENT))[lane];
        __half2* d1 = (__half2*)(Ain + e * AS + N_FEAT + lane * 4);
        d1[0] = __floats2half2_rn(v1.x, v1.y);
        d1[1] = __floats2half2_rn(v1.z, v1.w);
        __half2* d2 = (__half2*)(Ain + e * AS + N_FEAT + LATENT + lane * 4);
        d2[0] = __floats2half2_rn(v2.x, v2.y);
        d2[1] = __floats2half2_rn(v2.z, v2.w);
    }
    for (int idx = tid; idx < TILE_E * 24; idx += NCOMPUTE) {   // zero cols 272..319
        int e = idx / 24, c = D_IN + (idx % 24) * 2;
        *(uint32_t*)(Ain + e * AS + c) = 0u;
    }
    BAR_COMPUTE();

    const int mW  = (w & 1) * 64, nW  = (w >> 1) * 64;   // L1/L2: 64x64 warp tiles
    const int mW3 = (w & 3) * 32, nW3 = (w >> 2) * 64;   // L3:    32x64 warp tiles

    int cc = 0;
    int cph[2] = {0, 0};

    #pragma unroll 1
    for (int net = 0; net < 2; net++) {
        const float* B1 = net ? b1b : b1a;
        const float* B2 = net ? b2b : b2a;
        const float* B3 = net ? b3b : b3a;
        const int*   port = net ? p2 : p1;

        // ===== layer 1 =====
        {
            float acc[4][8][4] = {};
            consume_layer<4, 8>(sb + SM_A, AS, 5, mW, nW, lane, sW0, sW1, barB, cc, cph, acc);
            BAR_COMPUTE();
            #pragma unroll
            for (int mt = 0; mt < 4; mt++) {
                int r0 = mW + mt * 16 + (lane >> 2);
                #pragma unroll
                for (int nt = 0; nt < 8; nt++) {
                    int col = nW + nt * 8 + 2 * (lane & 3);
                    float bv0 = B1[col], bv1 = B1[col + 1];
                    *(__half2*)(Hh + r0 * HS + col) = __floats2half2_rn(
                        fmaxf(acc[mt][nt][0] + bv0, 0.f), fmaxf(acc[mt][nt][1] + bv1, 0.f));
                    *(__half2*)(Hh + (r0 + 8) * HS + col) = __floats2half2_rn(
                        fmaxf(acc[mt][nt][2] + bv0, 0.f), fmaxf(acc[mt][nt][3] + bv1, 0.f));
                }
            }
            BAR_COMPUTE();
        }

        // ===== layer 2 (in-place h) =====
        {
            float acc[4][8][4] = {};
            consume_layer<4, 8>(sb + SM_H, HS, 4, mW, nW, lane, sW0, sW1, barB, cc, cph, acc);
            BAR_COMPUTE();
            #pragma unroll
            for (int mt = 0; mt < 4; mt++) {
                int r0 = mW + mt * 16 + (lane >> 2);
                #pragma unroll
                for (int nt = 0; nt < 8; nt++) {
                    int col = nW + nt * 8 + 2 * (lane & 3);
                    float bv0 = B2[col], bv1 = B2[col + 1];
                    *(__half2*)(Hh + r0 * HS + col) = __floats2half2_rn(
                        fmaxf(acc[mt][nt][0] + bv0, 0.f), fmaxf(acc[mt][nt][1] + bv1, 0.f));
                    *(__half2*)(Hh + (r0 + 8) * HS + col) = __floats2half2_rn(
                        fmaxf(acc[mt][nt][2] + bv0, 0.f), fmaxf(acc[mt][nt][3] + bv1, 0.f));
                }
            }
            BAR_COMPUTE();
        }

        // ===== layer 3 + scatter =====
        {
            float acc[2][8][4] = {};
            consume_layer<2, 8>(sb + SM_H, HS, 4, mW3, nW3, lane, sW0, sW1, barB, cc, cph, acc);
            BAR_COMPUTE();   // all Hh reads done before net1 epilogue overwrites
            #pragma unroll
            for (int mt = 0; mt < 2; mt++) {
                int r0  = mW3 + mt * 16 + (lane >> 2);
                int ge0 = base + r0, ge1 = ge0 + 8;
                bool v0 = ge0 < N_EDGES, v1 = ge1 < N_EDGES;
                float nf0 = v0 ? nf[ge0] : 0.f;
                float nf1 = v1 ? nf[ge1] : 0.f;
                float* o0 = out + (size_t)(v0 ? port[ge0] : 0) * OUT_DIM;
                float* o1 = out + (size_t)(v1 ? port[ge1] : 0) * OUT_DIM;
                #pragma unroll
                for (int nt = 0; nt < 8; nt++) {
                    int col = nW3 + nt * 8 + 2 * (lane & 3);
                    float bv0 = B3[col], bv1 = B3[col + 1];
                    if (v0) red_add_v2(o0 + col, (acc[mt][nt][0] + bv0) * nf0,
                                                 (acc[mt][nt][1] + bv1) * nf0);
                    if (v1) red_add_v2(o1 + col, (acc[mt][nt][2] + bv0) * nf1,
                                                 (acc[mt][nt][3] + bv1) * nf1);
                }
            }
        }
    }
}

// ---------------------------------------------------------------------------
__global__ void zero_kernel(float4* __restrict__ out, int n4)
{
    int i = blockIdx.x * blockDim.x + threadIdx.x;
    if (i < n4) out[i] = make_float4(0.f, 0.f, 0.f, 0.f);
}

__global__ void tanh_kernel(float4* __restrict__ out, int n4)
{
    int i = blockIdx.x * blockDim.x + threadIdx.x;
    if (i < n4) {
        float4 v = out[i];
        v.x = tanhf(v.x); v.y = tanhf(v.y);
        v.z = tanhf(v.z); v.w = tanhf(v.w);
        out[i] = v;
    }
}

extern "C" void kernel_launch(void* const* d_in, const int* in_sizes, int n_in,
                              void* d_out, int out_size)
{
    const float* coords = (const float*)d_in[0];
    const float* ef     = (const float*)d_in[1];
    const float* nf     = (const float*)d_in[2];
    const int*   p1     = (const int*)  d_in[3];
    const int*   p2     = (const int*)  d_in[4];
    const float* W1a = (const float*)d_in[5];  const float* b1a = (const float*)d_in[6];
    const float* W2a = (const float*)d_in[7];  const float* b2a = (const float*)d_in[8];
    const float* W3a = (const float*)d_in[9];  const float* b3a = (const float*)d_in[10];
    const float* W1b = (const float*)d_in[11]; const float* b1b = (const float*)d_in[12];
    const float* W2b = (const float*)d_in[13]; const float* b2b = (const float*)d_in[14];
    const float* W3b = (const float*)d_in[15]; const float* b3b = (const float*)d_in[16];
    float* out = (float*)d_out;

    const int n  = N_NODES * OUT_DIM;
    const int n4 = n / 4;

    cudaFuncSetAttribute(edge_mlp_mma,
                         cudaFuncAttributeMaxDynamicSharedMemorySize, SM_TOTAL);

    prep_weights<<<352, 256>>>(W1a, W2a, W3a, W1b, W2b, W3b);
    zero_kernel<<<(n4 + 255) / 256, 256>>>((float4*)out, n4);

    const int grid = (N_EDGES + TILE_E - 1) / TILE_E;
    edge_mlp_mma<<<grid, NTHREADS, SM_TOTAL>>>(
        coords, ef, nf, p1, p2,
        b1a, b2a, b3a, b1b, b2b, b3b, out);

    tanh_kernel<<<(n4 + 255) / 256, 256>>>((float4*)out, n4);
}

// round 14
// speedup vs baseline: 1.5629x; 1.0466x over previous
#include <cuda_runtime.h>
#include <cuda_fp16.h>
#include <math.h>
#include <stdint.h>

#define N_NODES  100000
#define N_EDGES  250000
#define LATENT   128
#define N_FEAT   16
#define OUT_DIM  128
#define D_IN     272

#define TILE_E   128
#define NTHREADS 288          // 8 compute warps + 1 producer warp
#define NCOMPUTE 256

// ---- fp16 transposed weights: per net, [N rows][Kp cols] K-major ----
#define L1_KP      320
#define WT_L1_OFF  0
#define WT_L2_OFF  (256*320)                  // 81920
#define WT_L3_OFF  (WT_L2_OFF + 256*256)      // 147456
#define WT_PER_NET (WT_L3_OFF + 128*256)      // 180224

__device__ __align__(16) __half g_Wt[2 * WT_PER_NET];

// ---- smem strides (halves): odd 16B-segment counts -> conflict-free ldmatrix ----
#define AS 328
#define HS 264
#define WS 72

// ---- smem layout (bytes) ----
#define SM_A    0
#define SM_H    (TILE_E * AS * 2)              // 83968
#define SM_W0   (SM_H + TILE_E * HS * 2)       // 151552
#define SM_W1   (SM_W0 + 256 * WS * 2)         // 188416
#define SM_BAR  (SM_W1 + 256 * WS * 2)         // 225280
#define SM_TOTAL (SM_BAR + 32)                 // 225312

#define N_CHUNKS 26   // (5 + 4 + 4) per net x 2 nets

#define PREP_BLOCKS 352
#define ZERO_N4     (N_NODES * OUT_DIM / 4)    // 3.2M float4
#define ZERO_BLOCKS ((ZERO_N4 + 255) / 256)    // 12500

// ---------------------------------------------------------------------------
__device__ __forceinline__ uint32_t smem_u32(const void* p) {
    uint32_t a;
    asm("{ .reg .u64 t; cvta.to.shared.u64 t, %1; cvt.u32.u64 %0, t; }"
        : "=r"(a) : "l"(p));
    return a;
}

__device__ __forceinline__ void cp16(uint32_t s, const __half* g) {
    asm volatile("cp.async.ca.shared.global [%0], [%1], 16;"
                 :: "r"(s), "l"(__cvta_generic_to_global((const void*)g)) : "memory");
}

__device__ __forceinline__ void mbar_init(uint32_t addr, uint32_t cnt) {
    asm volatile("mbarrier.init.shared.b64 [%0], %1;" :: "r"(addr), "r"(cnt) : "memory");
}
__device__ __forceinline__ void mbar_arrive(uint32_t addr) {
    asm volatile("{\n\t.reg .b64 t;\n\tmbarrier.arrive.shared.b64 t, [%0];\n\t}"
                 :: "r"(addr) : "memory");
}
// .noinc is load-bearing: the default form pre-increments the pending count
// (net-zero on the phase), which deadlocks the consumers.
__device__ __forceinline__ void cp_mbar_arrive_noinc(uint32_t addr) {
    asm volatile("cp.async.mbarrier.arrive.noinc.shared.b64 [%0];" :: "r"(addr) : "memory");
}
// Spin wait (round-6 form; HW-sleep timeout variant measured slower).
__device__ __forceinline__ void mbar_wait(uint32_t addr, int parity) {
    uint32_t done = 0;
    while (!done) {
        asm volatile("{\n\t.reg .pred p;\n\t"
            "mbarrier.try_wait.parity.shared.b64 p, [%1], %2;\n\t"
            "selp.b32 %0, 1, 0, p;\n\t}"
            : "=r"(done) : "r"(addr), "r"((uint32_t)parity) : "memory");
    }
}
#define BAR_COMPUTE() asm volatile("bar.sync 1, 256;" ::: "memory")

#define LDSM_X4(r0, r1, r2, r3, addr) \
    asm volatile("ldmatrix.sync.aligned.m8n8.x4.shared.b16 {%0,%1,%2,%3}, [%4];" \
                 : "=r"(r0), "=r"(r1), "=r"(r2), "=r"(r3) : "r"(addr))

#define MMA16816(d, a, b0_, b1_) \
    asm volatile("mma.sync.aligned.m16n8k16.row.col.f32.f16.f16.f32 " \
                 "{%0,%1,%2,%3}, {%4,%5,%6,%7}, {%8,%9}, {%0,%1,%2,%3};" \
                 : "+f"((d)[0]), "+f"((d)[1]), "+f"((d)[2]), "+f"((d)[3]) \
                 : "r"((a)[0]), "r"((a)[1]), "r"((a)[2]), "r"((a)[3]), \
                   "r"(b0_), "r"(b1_))

__device__ __forceinline__ void red_add_v2(float* p, float a, float b) {
    asm volatile("red.global.add.v2.f32 [%0], {%1,%2};"
                 :: "l"(p), "f"(a), "f"(b) : "memory");
}

// ---------------------------------------------------------------------------
// fused prep + zero: blocks [0,352) transpose fp32 [K][N] weights into fp16
// [N][Kp] K-major scratch; blocks [352, 352+12500) zero the output buffer.
// Fusing overlaps the two and drops one serial launch.
// ---------------------------------------------------------------------------
__global__ void prep_and_zero(const float* __restrict__ W1a, const float* __restrict__ W2a,
                              const float* __restrict__ W3a, const float* __restrict__ W1b,
                              const float* __restrict__ W2b, const float* __restrict__ W3b,
                              float4* __restrict__ out)
{
    __shared__ float tile[32][33];
    int b = blockIdx.x;

    if (b >= PREP_BLOCKS) {
        int i = (b - PREP_BLOCKS) * blockDim.x + threadIdx.x;
        if (i < ZERO_N4) out[i] = make_float4(0.f, 0.f, 0.f, 0.f);
        return;
    }

    const int tx = threadIdx.x & 31, ty = threadIdx.x >> 5;   // 32 x 8
    const int net = b / 176;
    int r = b - net * 176;

    const float* src; int K, Kp, N, tk, tn, dstOff;
    if (r < 80)       { src = net ? W1b : W1a; K = D_IN; Kp = L1_KP; N = 256;
                        tk = r % 10; tn = r / 10; dstOff = WT_L1_OFF; }
    else if (r < 144) { r -= 80; src = net ? W2b : W2a; K = 256; Kp = 256; N = 256;
                        tk = r & 7; tn = r >> 3; dstOff = WT_L2_OFF; }
    else              { r -= 144; src = net ? W3b : W3a; K = 256; Kp = 256; N = 128;
                        tk = r & 7; tn = r >> 3; dstOff = WT_L3_OFF; }

    const int k0 = tk * 32, n0 = tn * 32;
    #pragma unroll
    for (int i = 0; i < 4; i++) {
        int k = k0 + ty + i * 8;
        tile[ty + i * 8][tx] = (k < K) ? src[(size_t)k * N + n0 + tx] : 0.0f;
    }
    __syncthreads();

    __half* dst = g_Wt + (size_t)net * WT_PER_NET + dstOff;
    #pragma unroll
    for (int i = 0; i < 4; i++) {
        int n = n0 + ty + i * 8;
        dst[(size_t)n * Kp + k0 + tx] = __float2half(tile[tx][ty + i * 8]);
    }
}

// ---------------------------------------------------------------------------
// consumer: one layer's chunks (mbarrier-gated), acc += A @ W^T
// ---------------------------------------------------------------------------
template<int MT, int NT>
__device__ __forceinline__ void consume_layer(
    uint32_t aBase, int aStride, int nch,
    int mWarp, int nWarp, int lane,
    uint32_t sW0, uint32_t sW1, uint32_t barB,
    int& cc, int (&cph)[2],
    float (&acc)[MT][NT][4])
{
    for (int c = 0; c < nch; c++, cc++) {
        const int s = cc & 1;
        mbar_wait(barB + 8 * s, cph[s]); cph[s] ^= 1;       // full[s]
        const uint32_t wB = s ? sW1 : sW0;
        const int kA = c * 64;
        #pragma unroll
        for (int ks = 0; ks < 4; ks++) {
            const int k = ks * 16;
            uint32_t a[MT][4];
            #pragma unroll
            for (int mt = 0; mt < MT; mt++) {
                int row = mWarp + mt * 16 + (lane & 15);
                int col = kA + k + ((lane >> 4) << 3);
                LDSM_X4(a[mt][0], a[mt][1], a[mt][2], a[mt][3],
                        aBase + (uint32_t)(row * aStride + col) * 2);
            }
            uint32_t b[4][4];
            #pragma unroll
            for (int np = 0; np < NT / 2; np++) {
                int rowB = nWarp + np * 16 + ((lane >> 4) << 3) + (lane & 7);
                int colB = k + (((lane >> 3) & 1) << 3);
                LDSM_X4(b[np][0], b[np][1], b[np][2], b[np][3],
                        wB + (uint32_t)(rowB * WS + colB) * 2);
            }
            #pragma unroll
            for (int np = 0; np < NT / 2; np++)
                #pragma unroll
                for (int mt = 0; mt < MT; mt++) {
                    MMA16816(acc[mt][2 * np],     a[mt], b[np][0], b[np][1]);
                    MMA16816(acc[mt][2 * np + 1], a[mt], b[np][2], b[np][3]);
                }
        }
        mbar_arrive(barB + 16 + 8 * s);                      // empty[s]
    }
}

// ---------------------------------------------------------------------------
// main fused kernel: 1 CTA = 128 edges; warp 8 = weight producer
// ---------------------------------------------------------------------------
__global__ void __launch_bounds__(NTHREADS, 1)
edge_mlp_mma(const float* __restrict__ coords,
             const float* __restrict__ ef,
             const float* __restrict__ nf,
             const int*   __restrict__ p1,
             const int*   __restrict__ p2,
             const float* __restrict__ b1a, const float* __restrict__ b2a,
             const float* __restrict__ b3a,
             const float* __restrict__ b1b, const float* __restrict__ b2b,
             const float* __restrict__ b3b,
             float* __restrict__ out)
{
    extern __shared__ char smem[];
    const uint32_t sb = smem_u32(smem);
    __half* Ain   = (__half*)(smem + SM_A);
    __half* Hh    = (__half*)(smem + SM_H);
    const uint32_t sW0 = sb + SM_W0, sW1 = sb + SM_W1, barB = sb + SM_BAR;
    const int tid = threadIdx.x, w = tid >> 5, lane = tid & 31;
    const int base = blockIdx.x * TILE_E;

    if (tid == 0) {
        mbar_init(barB + 0, 32);   // full0  (producer lanes, cp-arrive noinc)
        mbar_init(barB + 8, 32);   // full1
        mbar_init(barB + 16, 256); // empty0 (compute threads)
        mbar_init(barB + 24, 256); // empty1
    }
    __syncthreads();

    // ======================= producer warp =======================
    if (w == 8) {
        int pph[2] = {0, 0};
        #pragma unroll 1
        for (int c = 0; c < N_CHUNKS; c++) {
            const int s = c & 1;
            if (c >= 2) { mbar_wait(barB + 16 + 8 * s, pph[s]); pph[s] ^= 1; }
            const int net = (c >= 13) ? 1 : 0;
            const int lc  = c - net * 13;
            const __half* src; int Kp, rows, k0;
            if (lc < 5)      { src = g_Wt + (size_t)net * WT_PER_NET + WT_L1_OFF; Kp = L1_KP; rows = 256; k0 = lc * 64; }
            else if (lc < 9) { src = g_Wt + (size_t)net * WT_PER_NET + WT_L2_OFF; Kp = 256;  rows = 256; k0 = (lc - 5) * 64; }
            else             { src = g_Wt + (size_t)net * WT_PER_NET + WT_L3_OFF; Kp = 256;  rows = 128; k0 = (lc - 9) * 64; }
            const uint32_t dst = s ? sW1 : sW0;
            for (int i = lane; i < rows * 8; i += 32) {
                int n = i >> 3, seg = i & 7;
                cp16(dst + (uint32_t)(n * WS + seg * 8) * 2,
                     src + (size_t)n * Kp + k0 + seg * 8);
            }
            cp_mbar_arrive_noinc(barB + 8 * s);   // full[s] fires when this lane's cps land
        }
        return;
    }

    // ======================= compute warps (0..7) =======================
    // ---- gather: A[e] = [ef(16) | c1(128) | c2(128) | pad(48)] as fp16 ----
    for (int idx = tid; idx < TILE_E * N_FEAT; idx += NCOMPUTE) {
        int e = idx >> 4, k = idx & 15;
        int ge = base + e; if (ge >= N_EDGES) ge = N_EDGES - 1;
        Ain[e * AS + k] = __float2half(ef[(size_t)ge * N_FEAT + k]);
    }
    // two rows in flight per warp -> higher gather MLP
    for (int e = w; e < TILE_E; e += 16) {
        int eB = e + 8;
        int geA = base + e;  if (geA >= N_EDGES) geA = N_EDGES - 1;
        int geB = base + eB; if (geB >= N_EDGES) geB = N_EDGES - 1;
        const float4 a1 = ((const float4*)(coords + (size_t)p1[geA] * LATENT))[lane];
        const float4 a2 = ((const float4*)(coords + (size_t)p2[geA] * LATENT))[lane];
        const float4 c1 = ((const float4*)(coords + (size_t)p1[geB] * LATENT))[lane];
        const float4 c2 = ((const float4*)(coords + (size_t)p2[geB] * LATENT))[lane];
        __half2* dA1 = (__half2*)(Ain + e * AS + N_FEAT + lane * 4);
        dA1[0] = __floats2half2_rn(a1.x, a1.y);
        dA1[1] = __floats2half2_rn(a1.z, a1.w);
        __half2* dA2 = (__half2*)(Ain + e * AS + N_FEAT + LATENT + lane * 4);
        dA2[0] = __floats2half2_rn(a2.x, a2.y);
        dA2[1] = __floats2half2_rn(a2.z, a2.w);
        __half2* dB1 = (__half2*)(Ain + eB * AS + N_FEAT + lane * 4);
        dB1[0] = __floats2half2_rn(c1.x, c1.y);
        dB1[1] = __floats2half2_rn(c1.z, c1.w);
        __half2* dB2 = (__half2*)(Ain + eB * AS + N_FEAT + LATENT + lane * 4);
        dB2[0] = __floats2half2_rn(c2.x, c2.y);
        dB2[1] = __floats2half2_rn(c2.z, c2.w);
    }
    for (int idx = tid; idx < TILE_E * 24; idx += NCOMPUTE) {   // zero cols 272..319
        int e = idx / 24, c = D_IN + (idx % 24) * 2;
        *(uint32_t*)(Ain + e * AS + c) = 0u;
    }
    BAR_COMPUTE();

    const int mW  = (w & 1) * 64, nW  = (w >> 1) * 64;   // L1/L2: 64x64 warp tiles
    const int mW3 = (w & 3) * 32, nW3 = (w >> 2) * 64;   // L3:    32x64 warp tiles

    int cc = 0;
    int cph[2] = {0, 0};

    #pragma unroll 1
    for (int net = 0; net < 2; net++) {
        const float* B1 = net ? b1b : b1a;
        const float* B2 = net ? b2b : b2a;
        const float* B3 = net ? b3b : b3a;
        const int*   port = net ? p2 : p1;

        // ===== layer 1 =====
        {
            float acc[4][8][4] = {};
            consume_layer<4, 8>(sb + SM_A, AS, 5, mW, nW, lane, sW0, sW1, barB, cc, cph, acc);
            // no barrier needed here: Hh has no concurrent readers at this
            // point (net0: region fresh; net1: net0-L3 reads were ordered by
            // its pre-scatter barrier). Each warp writes only its own block.
            #pragma unroll
            for (int mt = 0; mt < 4; mt++) {
                int r0 = mW + mt * 16 + (lane >> 2);
                #pragma unroll
                for (int nt = 0; nt < 8; nt++) {
                    int col = nW + nt * 8 + 2 * (lane & 3);
                    float bv0 = B1[col], bv1 = B1[col + 1];
                    *(__half2*)(Hh + r0 * HS + col) = __floats2half2_rn(
                        fmaxf(acc[mt][nt][0] + bv0, 0.f), fmaxf(acc[mt][nt][1] + bv1, 0.f));
                    *(__half2*)(Hh + (r0 + 8) * HS + col) = __floats2half2_rn(
                        fmaxf(acc[mt][nt][2] + bv0, 0.f), fmaxf(acc[mt][nt][3] + bv1, 0.f));
                }
            }
            BAR_COMPUTE();   // Hh writes visible before L2 consume reads
        }

        // ===== layer 2 (in-place h) =====
        {
            float acc[4][8][4] = {};
            consume_layer<4, 8>(sb + SM_H, HS, 4, mW, nW, lane, sW0, sW1, barB, cc, cph, acc);
            BAR_COMPUTE();   // all Hh reads done before in-place overwrite
            #pragma unroll
            for (int mt = 0; mt < 4; mt++) {
                int r0 = mW + mt * 16 + (lane >> 2);
                #pragma unroll
                for (int nt = 0; nt < 8; nt++) {
                    int col = nW + nt * 8 + 2 * (lane & 3);
                    float bv0 = B2[col], bv1 = B2[col + 1];
                    *(__half2*)(Hh + r0 * HS + col) = __floats2half2_rn(
                        fmaxf(acc[mt][nt][0] + bv0, 0.f), fmaxf(acc[mt][nt][1] + bv1, 0.f));
                    *(__half2*)(Hh + (r0 + 8) * HS + col) = __floats2half2_rn(
                        fmaxf(acc[mt][nt][2] + bv0, 0.f), fmaxf(acc[mt][nt][3] + bv1, 0.f));
                }
            }
            BAR_COMPUTE();
        }

        // ===== layer 3 + scatter =====
        {
            float acc[2][8][4] = {};
            consume_layer<2, 8>(sb + SM_H, HS, 4, mW3, nW3, lane, sW0, sW1, barB, cc, cph, acc);
            BAR_COMPUTE();   // all Hh reads done before net1 epilogue overwrites
            #pragma unroll
            for (int mt = 0; mt < 2; mt++) {
                int r0  = mW3 + mt * 16 + (lane >> 2);
                int ge0 = base + r0, ge1 = ge0 + 8;
                bool v0 = ge0 < N_EDGES, v1 = ge1 < N_EDGES;
                float nf0 = v0 ? nf[ge0] : 0.f;
                float nf1 = v1 ? nf[ge1] : 0.f;
                float* o0 = out + (size_t)(v0 ? port[ge0] : 0) * OUT_DIM;
                float* o1 = out + (size_t)(v1 ? port[ge1] : 0) * OUT_DIM;
                #pragma unroll
                for (int nt = 0; nt < 8; nt++) {
                    int col = nW3 + nt * 8 + 2 * (lane & 3);
                    float bv0 = B3[col], bv1 = B3[col + 1];
                    if (v0) red_add_v2(o0 + col, (acc[mt][nt][0] + bv0) * nf0,
                                                 (acc[mt][nt][1] + bv1) * nf0);
                    if (v1) red_add_v2(o1 + col, (acc[mt][nt][2] + bv0) * nf1,
                                                 (acc[mt][nt][3] + bv1) * nf1);
                }
            }
        }
    }
}

// ---------------------------------------------------------------------------
__global__ void tanh_kernel(float4* __restrict__ out, int n4)
{
    int i = blockIdx.x * blockDim.x + threadIdx.x;
    if (i < n4) {
        float4 v = out[i];
        v.x = tanhf(v.x); v.y = tanhf(v.y);
        v.z = tanhf(v.z); v.w = tanhf(v.w);
        out[i] = v;
    }
}

extern "C" void kernel_launch(void* const* d_in, const int* in_sizes, int n_in,
                              void* d_out, int out_size)
{
    const float* coords = (const float*)d_in[0];
    const float* ef     = (const float*)d_in[1];
    const float* nf     = (const float*)d_in[2];
    const int*   p1     = (const int*)  d_in[3];
    const int*   p2     = (const int*)  d_in[4];
    const float* W1a = (const float*)d_in[5];  const float* b1a = (const float*)d_in[6];
    const float* W2a = (const float*)d_in[7];  const float* b2a = (const float*)d_in[8];
    const float* W3a = (const float*)d_in[9];  const float* b3a = (const float*)d_in[10];
    const float* W1b = (const float*)d_in[11]; const float* b1b = (const float*)d_in[12];
    const float* W2b = (const float*)d_in[13]; const float* b2b = (const float*)d_in[14];
    const float* W3b = (const float*)d_in[15]; const float* b3b = (const float*)d_in[16];
    float* out = (float*)d_out;

    cudaFuncSetAttribute(edge_mlp_mma,
                         cudaFuncAttributeMaxDynamicSharedMemorySize, SM_TOTAL);

    prep_and_zero<<<PREP_BLOCKS + ZERO_BLOCKS, 256>>>(
        W1a, W2a, W3a, W1b, W2b, W3b, (float4*)out);

    const int grid = (N_EDGES + TILE_E - 1) / TILE_E;
    edge_mlp_mma<<<grid, NTHREADS, SM_TOTAL>>>(
        coords, ef, nf, p1, p2,
        b1a, b2a, b3a, b1b, b2b, b3b, out);

    tanh_kernel<<<(ZERO_N4 + 255) / 256, 256>>>((float4*)out, ZERO_N4);
}